// round 1
// baseline (speedup 1.0000x reference)
#include <cuda_runtime.h>
#include <math_constants.h>

#define Bb 4
#define Cc 64
#define C2c 32
#define Nn 1024
#define Vv 20
#define Pp (Bb*Nn*Vv)          // 81920 points
#define NVv (Nn*Vv)            // 20480
#define BNb (Bb*Nn)            // 4096
#define OUTSZ (Bb*Cc*Nn*Vv)    // 5242880
#define EPSc 1e-5f

// -------- scratch (device globals; no allocation allowed) --------
__device__ float g_xm[C2c*Pp];        // masked embed pre-BN, layout [c2][p]
__device__ float g_u[OUTSZ];          // u, layout matches output (b,o,n,v)
__device__ float g_T[Bb*Cc*Nn];       // max_v t, layout [b][o][n]
__device__ float g_est[64];           // embed: sum[0:32], sumsq[32:64]
__device__ float g_cst[320];          // conv: S1,S2,S3,S4,C each [64]
__device__ float g_bnA[64];           // embed: scale[0:32], shift[32:64]
__device__ float g_bnB[128];          // conv: scale[0:64], shift[64:128]

// -------- f32x2 helpers --------
__device__ __forceinline__ unsigned long long dup2(float x) {
    unsigned long long r;
    asm("mov.b64 %0, {%1, %1};" : "=l"(r) : "f"(x));
    return r;
}
__device__ __forceinline__ void fma2(unsigned long long& d, unsigned long long a, unsigned long long b) {
    asm("fma.rn.f32x2 %0, %1, %2, %0;" : "+l"(d) : "l"(a), "l"(b));
}
__device__ __forceinline__ float2 unpk2(unsigned long long v) {
    float2 r;
    asm("mov.b64 {%0, %1}, %2;" : "=f"(r.x), "=f"(r.y) : "l"(v));
    return r;
}

// ==================== K0: zero accumulators ====================
__global__ void k0_zero() {
    int t = threadIdx.x;
    if (t < 64) g_est[t] = 0.f;
    else if (t < 384) g_cst[t - 64] = 0.f;
}

// ==================== K1: embed GEMM + masked stats ====================
// xm[c2][p] = mask[p] * (sum_c feats[b,c,nv] * wE[c2,c] + bE[c2])
__global__ void __launch_bounds__(256) k1_embed(
    const float* __restrict__ feats, const float* __restrict__ mask,
    const float* __restrict__ wE, const float* __restrict__ bE)
{
    __shared__ float wsh[Cc*C2c];   // [c][o], pairs (2j,2j+1) adjacent for f32x2
    int tid = threadIdx.x;
    for (int j = tid; j < Cc*C2c; j += 256) {
        int o = j >> 6, c = j & 63;
        wsh[c*C2c + o] = wE[j];
    }
    __syncthreads();

    int p  = blockIdx.x * 256 + tid;          // grid exact: 320*256 = 81920
    int b  = p / NVv;
    int nv = p - b * NVv;
    const float* fptr = feats + (size_t)b * Cc * NVv + nv;
    const unsigned long long* wsh2 = (const unsigned long long*)wsh;

    unsigned long long acc[16];
    #pragma unroll
    for (int j = 0; j < 16; ++j) acc[j] = 0ULL;

    #pragma unroll 4
    for (int c = 0; c < Cc; ++c) {
        float f = __ldg(fptr + c * NVv);
        unsigned long long f2 = dup2(f);
        #pragma unroll
        for (int j = 0; j < 16; ++j) fma2(acc[j], wsh2[c*16 + j], f2);
    }

    float m = __ldg(mask + p);
    int lane = tid & 31;

    #pragma unroll
    for (int j = 0; j < 16; ++j) {
        float2 v = unpk2(acc[j]);
        int o0 = 2*j, o1 = 2*j + 1;
        float x0 = (v.x + __ldg(bE + o0)) * m;
        float x1 = (v.y + __ldg(bE + o1)) * m;
        g_xm[o0*Pp + p] = x0;
        g_xm[o1*Pp + p] = x1;
        float s0 = x0, q0 = x0*x0, s1 = x1, q1 = x1*x1;
        #pragma unroll
        for (int d = 16; d; d >>= 1) {
            s0 += __shfl_xor_sync(0xffffffffu, s0, d);
            q0 += __shfl_xor_sync(0xffffffffu, q0, d);
            s1 += __shfl_xor_sync(0xffffffffu, s1, d);
            q1 += __shfl_xor_sync(0xffffffffu, q1, d);
        }
        if (lane == 0) {
            atomicAdd(&g_est[o0], s0);      atomicAdd(&g_est[32 + o0], q0);
            atomicAdd(&g_est[o1], s1);      atomicAdd(&g_est[32 + o1], q1);
        }
    }
}

// ==================== K2: finalize embed BN ====================
__global__ void k2_finA(const float* __restrict__ gE, const float* __restrict__ beE) {
    int o = threadIdx.x;  // 32
    float cnt = (float)Pp;
    float mean = g_est[o] / cnt;
    float var  = g_est[32 + o] / cnt - mean * mean;
    float rs   = rsqrtf(var + EPSc);
    float sc   = rs * gE[o];
    g_bnA[o] = sc;
    g_bnA[32 + o] = beE[o] - mean * sc;
}

// ==================== K3: u/t GEMV + conv stats + T ====================
// one block per (b,n). 128 threads: tid<64 -> u-row o=tid (W1-W2), else t-row o=tid-64 (W2).
__global__ void __launch_bounds__(128) k3_conv(
    const float* __restrict__ mask, const float* __restrict__ wC)
{
    __shared__ float wsh[64*65];                 // padded: row o at o*65
    __shared__ __align__(16) float xs[C2c*Vv];   // x tile, [c2][v]
    __shared__ float rsum[128];

    int tid = threadIdx.x;
    int bid = blockIdx.x;
    int b = bid >> 10, n = bid & 1023;
    int p0 = bid * Vv;                           // = b*NVv + n*Vv

    for (int j = tid; j < 64*64; j += 128)
        wsh[(j >> 6) * 65 + (j & 63)] = wC[j];

    for (int i = tid; i < C2c*Vv; i += 128) {
        int c2 = i / Vv, v = i - c2 * Vv;
        float val = g_xm[c2*Pp + p0 + v];
        float x = fmaxf(fmaf(val, g_bnA[c2], g_bnA[32 + c2]), 0.f) * __ldg(mask + p0 + v);
        xs[c2*Vv + v] = x;
    }
    __syncthreads();

    int o2 = tid;
    bool isU = o2 < 64;
    int o = isU ? o2 : o2 - 64;

    unsigned long long wd[32];
    if (isU) {
        #pragma unroll
        for (int c2 = 0; c2 < 32; ++c2)
            wd[c2] = dup2(wsh[o*65 + c2] - wsh[o*65 + 32 + c2]);
    } else {
        #pragma unroll
        for (int c2 = 0; c2 < 32; ++c2)
            wd[c2] = dup2(wsh[o*65 + 32 + c2]);
    }

    unsigned long long acc[10];
    #pragma unroll
    for (int vp = 0; vp < 10; ++vp) acc[vp] = 0ULL;

    const unsigned long long* xs2 = (const unsigned long long*)xs;
    #pragma unroll
    for (int c2 = 0; c2 < 32; ++c2) {
        #pragma unroll
        for (int vp = 0; vp < 10; ++vp) fma2(acc[vp], wd[c2], xs2[c2*10 + vp]);
    }

    float a[20];
    #pragma unroll
    for (int vp = 0; vp < 10; ++vp) {
        float2 v = unpk2(acc[vp]);
        a[2*vp] = v.x; a[2*vp + 1] = v.y;
    }

    float s = 0.f, q = 0.f, mx = -CUDART_INF_F;
    #pragma unroll
    for (int v = 0; v < 20; ++v) { s += a[v]; q += a[v]*a[v]; mx = fmaxf(mx, a[v]); }
    rsum[o2] = s;

    if (isU) {
        size_t base = ((size_t)(b*Cc + o) * Nn + n) * Vv;   // 80-byte aligned
        float4* up = (float4*)(g_u + base);
        #pragma unroll
        for (int k = 0; k < 5; ++k)
            up[k] = make_float4(a[4*k], a[4*k+1], a[4*k+2], a[4*k+3]);
    } else {
        g_T[(b*Cc + o) * Nn + n] = mx;
    }
    __syncthreads();

    if (isU) {
        atomicAdd(&g_cst[o],        s);
        atomicAdd(&g_cst[64  + o],  q);
        atomicAdd(&g_cst[256 + o],  s * rsum[o2 + 64]);   // cross term
    } else {
        atomicAdd(&g_cst[128 + o],  s);
        atomicAdd(&g_cst[192 + o],  q);
    }
}

// ==================== K4: finalize conv BN ====================
__global__ void k4_finB(const float* __restrict__ gC, const float* __restrict__ beC) {
    int o = threadIdx.x;  // 64
    float S1 = g_cst[o], S2 = g_cst[64+o], S3 = g_cst[128+o], S4 = g_cst[192+o], Cx = g_cst[256+o];
    float M = (float)Bb * Nn * Vv * Vv;   // 1638400
    float sumy  = (float)Vv * (S1 + S3);
    float sumy2 = (float)Vv * (S2 + S4) + 2.f * Cx;
    float mean = sumy / M;
    float var  = sumy2 / M - mean * mean;
    float rs   = rsqrtf(var + EPSc);
    float sc   = rs * gC[o];
    g_bnB[o] = sc;
    g_bnB[64 + o] = beC[o] - mean * sc;
}

// ==================== K5: epilogue ====================
// out = feats + mask * relu((u + T) * scale + shift)
__global__ void __launch_bounds__(256) k5_out(
    const float* __restrict__ feats, const float* __restrict__ mask,
    float* __restrict__ out)
{
    int idx = blockIdx.x * 256 + threadIdx.x;     // grid exact: 20480*256
    int bo = idx / NVv;
    int wi = idx - bo * NVv;
    int b  = bo >> 6, o = bo & 63;
    float u = g_u[idx];
    float T = g_T[bo * Nn + wi / Vv];
    float m = __ldg(mask + b * NVv + wi);
    float z = fmaf(u + T, g_bnB[o], g_bnB[64 + o]);
    out[idx] = __ldg(feats + idx) + m * fmaxf(z, 0.f);
}

// ==================== launch ====================
extern "C" void kernel_launch(void* const* d_in, const int* in_sizes, int n_in,
                              void* d_out, int out_size) {
    const float* feats = (const float*)d_in[0];
    const float* mask  = (const float*)d_in[1];
    const float* wE    = (const float*)d_in[2];
    const float* bE    = (const float*)d_in[3];
    const float* gE    = (const float*)d_in[4];
    const float* beE   = (const float*)d_in[5];
    const float* wC    = (const float*)d_in[6];
    const float* gC    = (const float*)d_in[7];
    const float* beC   = (const float*)d_in[8];
    float* out = (float*)d_out;

    k0_zero<<<1, 384>>>();
    k1_embed<<<Pp/256, 256>>>(feats, mask, wE, bE);
    k2_finA<<<1, 32>>>(gE, beE);
    k3_conv<<<BNb, 128>>>(mask, wC);
    k4_finB<<<1, 64>>>(gC, beC);
    k5_out<<<OUTSZ/256, 256>>>(feats, mask, out);
}

// round 3
// speedup vs baseline: 2.9882x; 2.9882x over previous
#include <cuda_runtime.h>
#include <math_constants.h>

#define Bb 4
#define Cc 64
#define C2c 32
#define Nn 1024
#define Vv 20
#define Pp (Bb*Nn*Vv)          // 81920 points
#define NVv (Nn*Vv)            // 20480
#define BNb (Bb*Nn)            // 4096
#define OUTSZ (Bb*Cc*Nn*Vv)    // 5242880
#define EPSc 1e-5f

// -------- scratch (device globals; no allocation allowed) --------
__device__ float g_xm[C2c*Pp];        // masked embed pre-BN, layout [c2][p]
__device__ float g_u[OUTSZ];          // u, layout (b,o,n,v) == output layout
__device__ float g_T[Bb*Cc*Nn];       // max_v t, layout [b][o][n]
__device__ float g_est[64];           // embed: sum[0:32], sumsq[32:64]
__device__ float g_cst[320];          // conv: S1,S2,S3,S4,Cx each [64]

// -------- f32x2 helpers --------
__device__ __forceinline__ unsigned long long dup2(float x) {
    unsigned long long r;
    asm("mov.b64 %0, {%1, %1};" : "=l"(r) : "f"(x));
    return r;
}
__device__ __forceinline__ void fma2(unsigned long long& d, unsigned long long a, unsigned long long b) {
    asm("fma.rn.f32x2 %0, %1, %2, %0;" : "+l"(d) : "l"(a), "l"(b));
}
__device__ __forceinline__ float2 unpk2(unsigned long long v) {
    float2 r;
    asm("mov.b64 {%0, %1}, %2;" : "=f"(r.x), "=f"(r.y) : "l"(v));
    return r;
}

// ==================== K0: zero accumulators ====================
__global__ void k0_zero() {
    int t = threadIdx.x;
    if (t < 64) g_est[t] = 0.f;
    else if (t < 384) g_cst[t - 64] = 0.f;
}

// ==================== K1: embed GEMM + masked stats ====================
// 2 consecutive points per thread. xm = mask * (feats . wE^T + bE)
__global__ void __launch_bounds__(128) k1_embed(
    const float* __restrict__ feats, const float* __restrict__ mask,
    const float* __restrict__ wE, const float* __restrict__ bE)
{
    __shared__ float wsh[Cc*C2c];   // [c][o]; (2j,2j+1) adjacent -> f32x2
    __shared__ float sacc[64];      // block stats: sum[0:32], sq[32:64]
    int tid = threadIdx.x;
    for (int j = tid; j < Cc*C2c; j += 128) {
        int o = j >> 6, c = j & 63;
        wsh[c*C2c + o] = wE[j];
    }
    if (tid < 64) sacc[tid] = 0.f;
    __syncthreads();

    int t  = blockIdx.x * 128 + tid;         // 320*128 = 40960 thread-pairs
    int p0 = 2 * t;                           // even; same b for p0,p0+1
    int b  = p0 / NVv;
    int nv = p0 - b * NVv;
    const float* fptr = feats + (size_t)b * Cc * NVv + nv;
    const unsigned long long* wsh2 = (const unsigned long long*)wsh;

    unsigned long long accA[16], accB[16];
    #pragma unroll
    for (int j = 0; j < 16; ++j) { accA[j] = 0ULL; accB[j] = 0ULL; }

    #pragma unroll 4
    for (int c = 0; c < Cc; ++c) {
        float2 f = *(const float2*)(fptr + c * NVv);
        unsigned long long fa = dup2(f.x), fb = dup2(f.y);
        #pragma unroll
        for (int j = 0; j < 16; ++j) {
            unsigned long long w = wsh2[c*16 + j];
            fma2(accA[j], w, fa);
            fma2(accB[j], w, fb);
        }
    }

    float m0 = __ldg(mask + p0), m1 = __ldg(mask + p0 + 1);
    int lane = tid & 31;

    #pragma unroll
    for (int j = 0; j < 16; ++j) {
        float2 va = unpk2(accA[j]);      // point p0: (o0, o1)
        float2 vb = unpk2(accB[j]);      // point p0+1
        int o0 = 2*j, o1 = 2*j + 1;
        float b0 = __ldg(bE + o0), b1 = __ldg(bE + o1);
        float x00 = (va.x + b0) * m0;    // (o0,p0)
        float x01 = (vb.x + b0) * m1;    // (o0,p1)
        float x10 = (va.y + b1) * m0;    // (o1,p0)
        float x11 = (vb.y + b1) * m1;    // (o1,p1)
        *(float2*)(g_xm + (size_t)o0*Pp + p0) = make_float2(x00, x01);
        *(float2*)(g_xm + (size_t)o1*Pp + p0) = make_float2(x10, x11);
        float s0 = x00 + x01, q0 = x00*x00 + x01*x01;
        float s1 = x10 + x11, q1 = x10*x10 + x11*x11;
        #pragma unroll
        for (int d = 16; d; d >>= 1) {
            s0 += __shfl_xor_sync(0xffffffffu, s0, d);
            q0 += __shfl_xor_sync(0xffffffffu, q0, d);
            s1 += __shfl_xor_sync(0xffffffffu, s1, d);
            q1 += __shfl_xor_sync(0xffffffffu, q1, d);
        }
        if (lane == 0) {
            atomicAdd(&sacc[o0], s0);      atomicAdd(&sacc[32 + o0], q0);
            atomicAdd(&sacc[o1], s1);      atomicAdd(&sacc[32 + o1], q1);
        }
    }
    __syncthreads();
    if (tid < 64) atomicAdd(&g_est[tid], sacc[tid]);
}

// ==================== K3: u/t GEMV + conv stats + T ====================
// 512 blocks x 128 threads; each block processes 8 (b,n) tiles.
// tid<64 -> u-row o=tid (W1-W2); tid>=64 -> t-row o=tid-64 (W2).
// Embed-BN affine is finalized inline per block (g_est is complete after K1).
#define K3_TILES 8
__global__ void __launch_bounds__(128) k3_conv(
    const float* __restrict__ mask, const float* __restrict__ wC,
    const float* __restrict__ gE, const float* __restrict__ beE)
{
    __shared__ float wsh[64*65];                 // padded weight rows
    __shared__ __align__(16) float xs[C2c*Vv];   // x tile [c2][v]
    __shared__ float rsum[128];
    __shared__ float bnA[64];                    // scale[0:32], shift[32:64]

    int tid = threadIdx.x;

    for (int j = tid; j < 64*64; j += 128)
        wsh[(j >> 6) * 65 + (j & 63)] = wC[j];

    if (tid < 32) {                              // finalize embed BN
        float inv = 1.f / (float)Pp;
        float mean = g_est[tid] * inv;
        float var  = g_est[32 + tid] * inv - mean * mean;
        float sc   = rsqrtf(var + EPSc) * __ldg(gE + tid);
        bnA[tid] = sc;
        bnA[32 + tid] = __ldg(beE + tid) - mean * sc;
    }
    __syncthreads();

    int o2 = tid;
    bool isU = o2 < 64;
    int o = isU ? o2 : o2 - 64;

    unsigned long long wd[32];
    if (isU) {
        #pragma unroll
        for (int c2 = 0; c2 < 32; ++c2)
            wd[c2] = dup2(wsh[o*65 + c2] - wsh[o*65 + 32 + c2]);
    } else {
        #pragma unroll
        for (int c2 = 0; c2 < 32; ++c2)
            wd[c2] = dup2(wsh[o*65 + 32 + c2]);
    }

    float accS = 0.f, accQ = 0.f, accX = 0.f;
    const unsigned long long* xs2 = (const unsigned long long*)xs;

    for (int it = 0; it < K3_TILES; ++it) {
        int tileId = blockIdx.x * K3_TILES + it;      // == b*Nn + n
        int p0 = tileId * Vv;

        #pragma unroll
        for (int k = 0; k < 5; ++k) {
            int i = tid + k * 128;                    // 640 = 128*5 exact
            int c2 = i / Vv, v = i - c2 * Vv;
            float val = g_xm[(size_t)c2*Pp + p0 + v];
            float x = fmaxf(fmaf(val, bnA[c2], bnA[32 + c2]), 0.f) * __ldg(mask + p0 + v);
            xs[c2*Vv + v] = x;
        }
        __syncthreads();

        unsigned long long acc[10];
        #pragma unroll
        for (int vp = 0; vp < 10; ++vp) acc[vp] = 0ULL;
        #pragma unroll
        for (int c2 = 0; c2 < 32; ++c2) {
            #pragma unroll
            for (int vp = 0; vp < 10; ++vp) fma2(acc[vp], wd[c2], xs2[c2*10 + vp]);
        }

        float a[20];
        #pragma unroll
        for (int vp = 0; vp < 10; ++vp) {
            float2 v = unpk2(acc[vp]);
            a[2*vp] = v.x; a[2*vp + 1] = v.y;
        }

        float s = 0.f, q = 0.f, mx = -CUDART_INF_F;
        #pragma unroll
        for (int v = 0; v < 20; ++v) { s += a[v]; q += a[v]*a[v]; mx = fmaxf(mx, a[v]); }
        rsum[o2] = s;

        if (isU) {
            size_t base = (size_t)(tileId + (size_t)o * BNb);  // careful: need (b,o,n)
            // g_u layout: ((b*Cc + o)*Nn + n)*Vv ; tileId = b*Nn + n
            int b = tileId >> 10, n = tileId & 1023;
            float4* up = (float4*)(g_u + ((size_t)(b*Cc + o) * Nn + n) * Vv);
            #pragma unroll
            for (int k = 0; k < 5; ++k)
                up[k] = make_float4(a[4*k], a[4*k+1], a[4*k+2], a[4*k+3]);
            (void)base;
        } else {
            int b = tileId >> 10, n = tileId & 1023;
            g_T[(b*Cc + o) * Nn + n] = mx;
        }
        __syncthreads();                             // rsum ready; xs reusable

        accS += s; accQ += q;
        if (isU) accX += s * rsum[o2 + 64];
    }

    if (isU) {
        atomicAdd(&g_cst[o],        accS);
        atomicAdd(&g_cst[64  + o],  accQ);
        atomicAdd(&g_cst[256 + o],  accX);
    } else {
        atomicAdd(&g_cst[128 + o],  accS);
        atomicAdd(&g_cst[192 + o],  accQ);
    }
}

// ==================== K5: epilogue (float4) ====================
// out = feats + mask * relu((u + T) * scale + shift)
// One float4 per thread; each 256-thread block covers exactly one (b,o)
// (5120 float4 per (b,o), 5120/256 = 20 blocks). Conv-BN finalized inline.
__global__ void __launch_bounds__(256) k5_out(
    const float* __restrict__ feats, const float* __restrict__ mask,
    const float* __restrict__ gC, const float* __restrict__ beC,
    float* __restrict__ out)
{
    __shared__ float2 bn;
    int idx4 = blockIdx.x * 256 + threadIdx.x;    // grid exact: 5120*256
    int row  = idx4 / 5;                          // (b,o,n) row of 5 float4
    int v4   = idx4 - row * 5;
    int bo   = row >> 10;
    int n    = row & 1023;
    int b    = bo >> 6, o = bo & 63;

    if (threadIdx.x == 0) {
        float S1 = g_cst[o], S2 = g_cst[64+o], S3 = g_cst[128+o],
              S4 = g_cst[192+o], Cx = g_cst[256+o];
        float M = (float)Bb * Nn * Vv * Vv;
        float sumy  = (float)Vv * (S1 + S3);
        float sumy2 = (float)Vv * (S2 + S4) + 2.f * Cx;
        float mean = sumy / M;
        float var  = sumy2 / M - mean * mean;
        float sc   = rsqrtf(var + EPSc) * __ldg(gC + o);
        bn = make_float2(sc, __ldg(beC + o) - mean * sc);
    }
    __syncthreads();

    float4 u4 = ((const float4*)g_u)[idx4];
    float  T  = g_T[row];
    float4 m4 = __ldg((const float4*)mask + (size_t)(b * Nn + n) * 5 + v4);
    float4 f4 = __ldg((const float4*)feats + idx4);
    float sc = bn.x, sh = bn.y;

    float4 r;
    r.x = f4.x + m4.x * fmaxf(fmaf(u4.x + T, sc, sh), 0.f);
    r.y = f4.y + m4.y * fmaxf(fmaf(u4.y + T, sc, sh), 0.f);
    r.z = f4.z + m4.z * fmaxf(fmaf(u4.z + T, sc, sh), 0.f);
    r.w = f4.w + m4.w * fmaxf(fmaf(u4.w + T, sc, sh), 0.f);
    ((float4*)out)[idx4] = r;
}

// ==================== launch ====================
extern "C" void kernel_launch(void* const* d_in, const int* in_sizes, int n_in,
                              void* d_out, int out_size) {
    const float* feats = (const float*)d_in[0];
    const float* mask  = (const float*)d_in[1];
    const float* wE    = (const float*)d_in[2];
    const float* bE    = (const float*)d_in[3];
    const float* gE    = (const float*)d_in[4];
    const float* beE   = (const float*)d_in[5];
    const float* wC    = (const float*)d_in[6];
    const float* gC    = (const float*)d_in[7];
    const float* beC   = (const float*)d_in[8];
    float* out = (float*)d_out;

    k0_zero<<<1, 384>>>();
    k1_embed<<<Pp/256, 128>>>(feats, mask, wE, bE);          // 320 blocks
    k3_conv<<<BNb/K3_TILES, 128>>>(mask, wC, gE, beE);       // 512 blocks
    k5_out<<<OUTSZ/1024, 256>>>(feats, mask, gC, beC, out);  // 5120 blocks
}